// round 13
// baseline (speedup 1.0000x reference)
#include <cuda_runtime.h>
#include <math.h>

#define C 128
#define H 256
#define W 256
#define HW (H * W)
#define YA 16
#define XA 16
#define NPART 4   // stats partials per channel
#define NBLK 512  // must be <= guaranteed-resident block count (4/SM * 148)

// Deterministic scratch + monotonic barrier ticket (no allocations allowed).
__device__ float2 g_ps[C * NPART];
__device__ unsigned int g_tk;  // zero-init at module load; never reset (monotonic)

// PyTorch bicubic convolution kernel, a = -0.75
__device__ __forceinline__ float cubic_w(float t) {
    const float a = -0.75f;
    float at = fabsf(t);
    float nr = ((a + 2.f) * at - (a + 3.f)) * at * at + 1.f;
    float fr = (((at - 5.f) * at + 8.f) * at - 4.f) * a;
    return at <= 1.f ? nr : (at < 2.f ? fr : 0.f);
}

// Row of the (3*S, 4) bicubic weight matrix with index clamping folded in.
__device__ __forceinline__ void bicubic_w4(int o_full, float inv_out_times_in, float w[4]) {
    float src = ((float)o_full + 0.5f) * inv_out_times_in - 0.5f;
    float fi0 = floorf(src);
    float t = src - fi0;
    int b = (int)fi0;
    w[0] = w[1] = w[2] = w[3] = 0.f;
#pragma unroll
    for (int k = -1; k <= 2; k++) {
        int idx = b + k;
        idx = idx < 0 ? 0 : (idx > 3 ? 3 : idx);
        w[idx] += cubic_w(t - (float)k);
    }
}

// Fused kernel: grid 512 x 256thr, all blocks co-resident (4 CTA/SM cap).
// Phase 1: per-block stats partial over the pre half + device-wide barrier.
// Phase 2: per-block channel norm: maps built once, 2 real + 2 pre chunks.
__global__ void __launch_bounds__(256, 4) fused_kernel(
    const float* __restrict__ x,
    const float* __restrict__ mtab,
    const float* __restrict__ stab,
    const float* __restrict__ weight,
    const float* __restrict__ bias,
    const int* __restrict__ d_ya,
    const int* __restrict__ d_xa,
    const int* __restrict__ d_pya,
    const int* __restrict__ d_pxa,
    float* __restrict__ out)
{
    __shared__ float rowm[4][W];   // mean patch rows projected onto output cols
    __shared__ float rowsi[4][W];  // (weight/std) patch rows projected
    __shared__ float wyt[32][4];   // per-row y-weights for the current chunk
    __shared__ float pm[16], psi[16];
    __shared__ float s_pmean, s_pstd, s_wgt, s_bias;
    __shared__ float ws[8], ws2[8];

    int b = blockIdx.x;
    int tx = threadIdx.x;   // 0..63 -> 4 cols each
    int ty = threadIdx.y;   // 0..3  -> row phase
    int tid = ty * 64 + tx;
    int col = tx * 4;

    // ================= Phase 1: stats partial =================
    {
        int cs = b >> 2;       // stats channel
        int part = b & 3;      // quarter
        const float4* px = (const float4*)(x + (unsigned)(C + cs) * HW +
                                           (unsigned)part * (HW / NPART));
        const int N4 = HW / NPART / 4;  // 4096
        float s = 0.f, s2 = 0.f;
#pragma unroll 4
        for (int i = tid; i < N4; i += 256) {
            float4 v = px[i];
            s += (v.x + v.y) + (v.z + v.w);
            s2 += (v.x * v.x + v.y * v.y) + (v.z * v.z + v.w * v.w);
        }
#pragma unroll
        for (int off = 16; off; off >>= 1) {
            s += __shfl_xor_sync(0xffffffffu, s, off);
            s2 += __shfl_xor_sync(0xffffffffu, s2, off);
        }
        int lane = tid & 31, wid = tid >> 5;
        if (lane == 0) { ws[wid] = s; ws2[wid] = s2; }
        __syncthreads();
        if (wid == 0 && lane < 8) {
            s = ws[lane];
            s2 = ws2[lane];
#pragma unroll
            for (int off = 4; off; off >>= 1) {
                s += __shfl_xor_sync(0xffu, s, off);
                s2 += __shfl_xor_sync(0xffu, s2, off);
            }
            if (lane == 0) g_ps[b] = make_float2(s, s2);
        }
        __syncthreads();
    }

    // ================= Device-wide barrier (all 512 blocks resident) =======
    if (tid == 0) {
        __threadfence();
        unsigned int t = atomicAdd(&g_tk, 1u);
        unsigned int target = (t / NBLK + 1u) * NBLK;  // epoch end (monotonic)
        while (atomicAdd(&g_tk, 0u) < target) {
            __nanosleep(64);
        }
    }
    __syncthreads();
    __threadfence();

    // ================= Phase 2: normalize channel c =================
    int c = b & 127;
    int q = b >> 7;  // 0..3: which pair of chunks this block owns

    if (tid == 0) {
        float s = 0.f, s2 = 0.f;
#pragma unroll
        for (int p = 0; p < NPART; p++) {
            float2 v = g_ps[c * NPART + p];
            s += v.x;
            s2 += v.y;
        }
        float n = (float)HW;
        float mean = s / n;
        float var = (s2 - n * mean * mean) / (n - 1.f);  // unbiased
        s_pmean = mean;
        s_pstd = sqrtf(var);
        s_wgt = weight[c];
        s_bias = bias[c];
    }
    __syncthreads();

    // 4x4 anchor patch (with pre-stat substitution)
    if (tid < 16) {
        int j = tid >> 2, i = tid & 3;
        int yst = min(max(*d_ya, 0), YA - 1);  // dynamic_slice start clamp
        int xst = min(max(*d_xa, 0), XA - 1);
        int ry = min(max(yst + j - 1, 0), YA - 1);  // edge padding
        int rx = min(max(xst + i - 1, 0), XA - 1);
        float mv, sv;
        if (ry == *d_pya && rx == *d_pxa) {
            mv = s_pmean;
            sv = s_pstd;
        } else {
            mv = mtab[(ry * XA + rx) * C + c];
            sv = stab[(ry * XA + rx) * C + c];
        }
        pm[tid] = mv;
        psi[tid] = s_wgt / sv;  // weight folded in
    }
    __syncthreads();

    // project patch through Wx for every output column (ONCE per block)
    {
        float wx[4];
        bicubic_w4(tid + W / 2, 4.0f / (3.0f * (float)W), wx);
#pragma unroll
        for (int y = 0; y < 4; y++) {
            rowm[y][tid] = pm[y * 4 + 0] * wx[0] + pm[y * 4 + 1] * wx[1] +
                           pm[y * 4 + 2] * wx[2] + pm[y * 4 + 3] * wx[3];
            rowsi[y][tid] = psi[y * 4 + 0] * wx[0] + psi[y * 4 + 1] * wx[1] +
                            psi[y * 4 + 2] * wx[2] + psi[y * 4 + 3] * wx[3];
        }
    }

    float bs = s_bias;
    float pmean = s_pmean;
    float kpre = s_wgt / s_pstd;

    const float* xr = x + (unsigned)c * HW;
    const float* xp = x + (unsigned)(C + c) * HW;
    float* outr = out + (unsigned)c * HW;
    float* outp = out + (unsigned)(C + c) * HW;

#pragma unroll
    for (int u = 0; u < 2; u++) {
        int chunk = q + u * 4;      // 0..7
        int r0 = chunk * 32;

        // y-weights for this chunk (rewrite wyt; sync both sides)
        __syncthreads();
        if (tid < 32) {
            float wy[4];
            bicubic_w4(r0 + tid + H / 2, 4.0f / (3.0f * (float)H), wy);
            wyt[tid][0] = wy[0]; wyt[tid][1] = wy[1];
            wyt[tid][2] = wy[2]; wyt[tid][3] = wy[3];
        }
        __syncthreads();

        // real half: 32 rows with bicubic maps
#pragma unroll
        for (int it = 0; it < 8; it++) {
            int lr = ty + it * 4;
            float w0 = wyt[lr][0], w1 = wyt[lr][1], w2 = wyt[lr][2], w3 = wyt[lr][3];

            float m[4], si[4];
#pragma unroll
            for (int j = 0; j < 4; j++) {
                m[j] = w0 * rowm[0][col + j] + w1 * rowm[1][col + j] +
                       w2 * rowm[2][col + j] + w3 * rowm[3][col + j];
                si[j] = w0 * rowsi[0][col + j] + w1 * rowsi[1][col + j] +
                        w2 * rowsi[2][col + j] + w3 * rowsi[3][col + j];
            }

            unsigned o = (unsigned)(r0 + lr) * W + col;
            float4 vr = *(const float4*)(xr + o);
            float4 orv;
            orv.x = (vr.x - m[0]) * si[0] + bs;
            orv.y = (vr.y - m[1]) * si[1] + bs;
            orv.z = (vr.z - m[2]) * si[2] + bs;
            orv.w = (vr.w - m[3]) * si[3] + bs;
            *(float4*)(outr + o) = orv;
        }

        // pre half: 32 rows pure streaming (same chunk rows)
#pragma unroll
        for (int it = 0; it < 8; it++) {
            unsigned o = (unsigned)(r0 + ty + it * 4) * W + col;
            float4 v = *(const float4*)(xp + o);
            float4 ov;
            ov.x = (v.x - pmean) * kpre + bs;
            ov.y = (v.y - pmean) * kpre + bs;
            ov.z = (v.z - pmean) * kpre + bs;
            ov.w = (v.w - pmean) * kpre + bs;
            *(float4*)(outp + o) = ov;
        }
    }
}

extern "C" void kernel_launch(void* const* d_in, const int* in_sizes, int n_in,
                              void* d_out, int out_size) {
    const float* x = (const float*)d_in[0];        // (2, C, H, W)
    const float* mtab = (const float*)d_in[1];     // (YA, XA, C)
    const float* stab = (const float*)d_in[2];     // (YA, XA, C)
    const float* weight = (const float*)d_in[3];   // (1, C, 1, 1)
    const float* bias = (const float*)d_in[4];     // (1, C, 1, 1)
    const int* ya = (const int*)d_in[5];
    const int* xa = (const int*)d_in[6];
    const int* pya = (const int*)d_in[7];
    const int* pxa = (const int*)d_in[8];
    float* out = (float*)d_out;

    fused_kernel<<<NBLK, dim3(64, 4)>>>(x, mtab, stab, weight, bias,
                                        ya, xa, pya, pxa, out);
}